// round 1
// baseline (speedup 1.0000x reference)
#include <cuda_runtime.h>
#include <math.h>

// Problem constants
#define BN   4096
#define TN   512
#define ZD   64
#define OU   128
#define BERT 768
#define TOUT 513   // T+1 trajectory points

// Scratch (device globals: no allocation allowed)
__device__ float gZaug[BN * ZD];
__device__ float gPartial[BN];

// ---------------------------------------------------------------------------
// Phase A: warp-per-row. h = bert@projW + b -> LN -> +sigma*eps -> denoiser
// -> z_aug (scratch), diff partials, and t=0 outputs.
// ---------------------------------------------------------------------------
__global__ __launch_bounds__(256) void phaseA_kernel(
    const float* __restrict__ bert, const float* __restrict__ eps,
    const float* __restrict__ projW, const float* __restrict__ projB,
    const float* __restrict__ lnG, const float* __restrict__ lnB,
    const float* __restrict__ lns,
    const float* __restrict__ dW1, const float* __restrict__ db1,
    const float* __restrict__ dW2, const float* __restrict__ db2,
    const float* __restrict__ decW, const float* __restrict__ decB,
    float* __restrict__ outPd, float* __restrict__ outSl)
{
    const unsigned FULL = 0xffffffffu;
    int warp = (blockIdx.x * blockDim.x + threadIdx.x) >> 5;
    int l = threadIdx.x & 31;
    if (warp >= BN) return;
    const int r = warp;
    const int c = 2 * l;           // this lane owns z-cols c, c+1

    // ---- h = bert[r] @ projW + projB (lane: 2 cols) ----
    const float* brow = bert + (size_t)r * BERT;
    float hx = 0.f, hy = 0.f;
    #pragma unroll 4
    for (int k = 0; k < BERT; k++) {
        float bv = __ldg(brow + k);
        float2 wv = *(const float2*)(projW + k * ZD + c);
        hx = fmaf(bv, wv.x, hx);
        hy = fmaf(bv, wv.y, hy);
    }
    hx += projB[c]; hy += projB[c + 1];

    // ---- LayerNorm over 64 ----
    float s = hx + hy;
    #pragma unroll
    for (int o = 16; o; o >>= 1) s += __shfl_xor_sync(FULL, s, o);
    float mu = s * (1.0f / 64.0f);
    float d0 = hx - mu, d1 = hy - mu;
    float ss = d0 * d0 + d1 * d1;
    #pragma unroll
    for (int o = 16; o; o >>= 1) ss += __shfl_xor_sync(FULL, ss, o);
    float var = ss * (1.0f / 64.0f);
    float rs = rsqrtf(var + 1e-5f);
    float zc0 = d0 * rs * lnG[c]     + lnB[c];
    float zc1 = d1 * rs * lnG[c + 1] + lnB[c + 1];

    // ---- noise ----
    float sigma = log1pf(expf(lns[0]));
    float zn0 = zc0 + sigma * eps[(size_t)r * ZD + c];
    float zn1 = zc1 + sigma * eps[(size_t)r * ZD + c + 1];

    // ---- a1 = silu(z_noisy @ dW1 + db1); lane: 4 cols j0..j0+3 ----
    int j0 = 4 * l;
    float4 a = *(const float4*)(db1 + j0);
    #pragma unroll 4
    for (int k2 = 0; k2 < 32; k2++) {
        float zva = __shfl_sync(FULL, zn0, k2);     // z[2*k2]
        float zvb = __shfl_sync(FULL, zn1, k2);     // z[2*k2+1]
        int k = 2 * k2;
        float4 w = *(const float4*)(dW1 + k * OU + j0);
        a.x = fmaf(zva, w.x, a.x); a.y = fmaf(zva, w.y, a.y);
        a.z = fmaf(zva, w.z, a.z); a.w = fmaf(zva, w.w, a.w);
        w = *(const float4*)(dW1 + (k + 1) * OU + j0);
        a.x = fmaf(zvb, w.x, a.x); a.y = fmaf(zvb, w.y, a.y);
        a.z = fmaf(zvb, w.z, a.z); a.w = fmaf(zvb, w.w, a.w);
    }
    // silu
    a.x = a.x / (1.f + expf(-a.x));
    a.y = a.y / (1.f + expf(-a.y));
    a.z = a.z / (1.f + expf(-a.z));
    a.w = a.w / (1.f + expf(-a.w));

    // ---- z_aug = a1 @ dW2 + db2; lane: 2 cols ----
    float za0 = db2[c], za1 = db2[c + 1];
    float a1v[4] = {a.x, a.y, a.z, a.w};
    #pragma unroll 2
    for (int k4 = 0; k4 < 32; k4++) {
        #pragma unroll
        for (int j = 0; j < 4; j++) {
            float hv = __shfl_sync(FULL, a1v[j], k4);  // a1[4*k4 + j]
            int k = 4 * k4 + j;
            float2 w = *(const float2*)(dW2 + k * ZD + c);
            za0 = fmaf(hv, w.x, za0);
            za1 = fmaf(hv, w.y, za1);
        }
    }

    // ---- diff_loss partial ----
    float dd = (za0 - zc0) * (za0 - zc0) + (za1 - zc1) * (za1 - zc1);
    #pragma unroll
    for (int o = 16; o; o >>= 1) dd += __shfl_xor_sync(FULL, dd, o);
    if (l == 0) gPartial[r] = dd;

    // ---- store z_aug ----
    *(float2*)(gZaug + (size_t)r * ZD + c) = make_float2(za0, za1);

    // ---- t=0 decoded outputs ----
    float pd = za0 * decW[c * 2 + 0] + za1 * decW[(c + 1) * 2 + 0];
    float sl = za0 * decW[c * 2 + 1] + za1 * decW[(c + 1) * 2 + 1];
    #pragma unroll
    for (int o = 16; o; o >>= 1) {
        pd += __shfl_xor_sync(FULL, pd, o);
        sl += __shfl_xor_sync(FULL, sl, o);
    }
    if (l == 0) {
        outPd[(size_t)r * TOUT] = pd + decB[0];
        outSl[(size_t)r * TOUT] = sl + decB[1];
    }
}

// ---------------------------------------------------------------------------
// diff_loss final reduction (deterministic, single CTA)
// ---------------------------------------------------------------------------
__global__ void reduceDiff_kernel(float* __restrict__ outDiff)
{
    __shared__ float sh[256];
    float s = 0.f;
    for (int i = threadIdx.x; i < BN; i += 256) s += gPartial[i];
    sh[threadIdx.x] = s;
    __syncthreads();
    for (int step = 128; step; step >>= 1) {
        if (threadIdx.x < step) sh[threadIdx.x] += sh[threadIdx.x + step];
        __syncthreads();
    }
    if (threadIdx.x == 0) outDiff[0] = sh[0] * (1.0f / ((float)BN * (float)ZD));
}

// ---------------------------------------------------------------------------
// Phase B: ODE scan. 128 CTAs x 256 threads; 32 rows per CTA (4 per warp).
// Warps are row-independent across all three GEMMs -> only __syncwarp in loop.
// ---------------------------------------------------------------------------
#define ROWS 32

__global__ __launch_bounds__(256, 1) void ode_kernel(
    const float* __restrict__ oW1, const float* __restrict__ ob1,
    const float* __restrict__ oW2, const float* __restrict__ ob2,
    const float* __restrict__ oW3, const float* __restrict__ ob3,
    const float* __restrict__ decW, const float* __restrict__ decB,
    float* __restrict__ outPd, float* __restrict__ outSl)
{
    extern __shared__ float sm[];
    float* sW1 = sm;                       // 64*128
    float* sW2 = sW1 + ZD * OU;            // 128*128
    float* sW3 = sW2 + OU * OU;            // 128*64
    float* sB1 = sW3 + OU * ZD;            // 128
    float* sB2 = sB1 + OU;                 // 128
    float* sB3 = sB2 + OU;                 // 64
    float* sD0 = sB3 + ZD;                 // 64
    float* sD1 = sD0 + ZD;                 // 64
    float* sZ  = sD1 + ZD;                 // 32*64
    float* sH1 = sZ + ROWS * ZD;           // 32*128
    float* sH2 = sH1 + ROWS * OU;          // 32*128

    const int tid = threadIdx.x;
    const int rowBase = blockIdx.x * ROWS;

    // cooperative weight/state loads (float4)
    for (int i = tid; i < (ZD * OU) / 4; i += 256) ((float4*)sW1)[i] = ((const float4*)oW1)[i];
    for (int i = tid; i < (OU * OU) / 4; i += 256) ((float4*)sW2)[i] = ((const float4*)oW2)[i];
    for (int i = tid; i < (OU * ZD) / 4; i += 256) ((float4*)sW3)[i] = ((const float4*)oW3)[i];
    if (tid < OU) { sB1[tid] = ob1[tid]; sB2[tid] = ob2[tid]; }
    if (tid < ZD) { sB3[tid] = ob3[tid]; sD0[tid] = decW[2 * tid]; sD1[tid] = decW[2 * tid + 1]; }
    for (int i = tid; i < (ROWS * ZD) / 4; i += 256)
        ((float4*)sZ)[i] = ((const float4*)(gZaug + (size_t)rowBase * ZD))[i];
    __syncthreads();

    const int w  = tid >> 5;
    const int l  = tid & 31;
    const int r0 = w * 4;
    const int c4 = l * 4;
    const int c2 = l * 2;
    const float dt = 1.0f / (float)TN;
    const float db0 = decB[0], db1v = decB[1];
    const unsigned FULL = 0xffffffffu;

    const float2 dv0 = *(const float2*)(sD0 + c2);
    const float2 dv1 = *(const float2*)(sD1 + c2);

    for (int t = 0; t < TN; t++) {
        // ===== GEMM1: h1 = tanh(z @ W1 + b1), K=64, cols 128 =====
        {
            float4 acc[4];
            float4 bb = *(const float4*)(sB1 + c4);
            #pragma unroll
            for (int rr = 0; rr < 4; rr++) acc[rr] = bb;
            #pragma unroll 2
            for (int k = 0; k < ZD; k += 4) {
                float4 zr[4];
                #pragma unroll
                for (int rr = 0; rr < 4; rr++)
                    zr[rr] = *(const float4*)(sZ + (r0 + rr) * ZD + k);
                #pragma unroll
                for (int kk = 0; kk < 4; kk++) {
                    float4 wv = *(const float4*)(sW1 + (k + kk) * OU + c4);
                    #pragma unroll
                    for (int rr = 0; rr < 4; rr++) {
                        float zv = (kk == 0) ? zr[rr].x : (kk == 1) ? zr[rr].y
                                 : (kk == 2) ? zr[rr].z : zr[rr].w;
                        acc[rr].x = fmaf(zv, wv.x, acc[rr].x);
                        acc[rr].y = fmaf(zv, wv.y, acc[rr].y);
                        acc[rr].z = fmaf(zv, wv.z, acc[rr].z);
                        acc[rr].w = fmaf(zv, wv.w, acc[rr].w);
                    }
                }
            }
            #pragma unroll
            for (int rr = 0; rr < 4; rr++) {
                float4 v = acc[rr];
                v.x = tanhf(v.x); v.y = tanhf(v.y);
                v.z = tanhf(v.z); v.w = tanhf(v.w);
                *(float4*)(sH1 + (r0 + rr) * OU + c4) = v;
            }
            __syncwarp();
        }

        // ===== GEMM2: h2 = tanh(h1 @ W2 + b2), K=128, cols 128 =====
        {
            float4 acc[4];
            float4 bb = *(const float4*)(sB2 + c4);
            #pragma unroll
            for (int rr = 0; rr < 4; rr++) acc[rr] = bb;
            #pragma unroll 2
            for (int k = 0; k < OU; k += 4) {
                float4 hr[4];
                #pragma unroll
                for (int rr = 0; rr < 4; rr++)
                    hr[rr] = *(const float4*)(sH1 + (r0 + rr) * OU + k);
                #pragma unroll
                for (int kk = 0; kk < 4; kk++) {
                    float4 wv = *(const float4*)(sW2 + (k + kk) * OU + c4);
                    #pragma unroll
                    for (int rr = 0; rr < 4; rr++) {
                        float hv = (kk == 0) ? hr[rr].x : (kk == 1) ? hr[rr].y
                                 : (kk == 2) ? hr[rr].z : hr[rr].w;
                        acc[rr].x = fmaf(hv, wv.x, acc[rr].x);
                        acc[rr].y = fmaf(hv, wv.y, acc[rr].y);
                        acc[rr].z = fmaf(hv, wv.z, acc[rr].z);
                        acc[rr].w = fmaf(hv, wv.w, acc[rr].w);
                    }
                }
            }
            #pragma unroll
            for (int rr = 0; rr < 4; rr++) {
                float4 v = acc[rr];
                v.x = tanhf(v.x); v.y = tanhf(v.y);
                v.z = tanhf(v.z); v.w = tanhf(v.w);
                *(float4*)(sH2 + (r0 + rr) * OU + c4) = v;
            }
            __syncwarp();
        }

        // ===== GEMM3: f = h2 @ W3 + b3 (cols 64), z update, decode =====
        {
            float2 f[4];
            float2 b3v = *(const float2*)(sB3 + c2);
            #pragma unroll
            for (int rr = 0; rr < 4; rr++) f[rr] = b3v;
            #pragma unroll 2
            for (int k = 0; k < OU; k += 4) {
                float4 hr[4];
                #pragma unroll
                for (int rr = 0; rr < 4; rr++)
                    hr[rr] = *(const float4*)(sH2 + (r0 + rr) * OU + k);
                #pragma unroll
                for (int kk = 0; kk < 4; kk++) {
                    float2 wv = *(const float2*)(sW3 + (k + kk) * ZD + c2);
                    #pragma unroll
                    for (int rr = 0; rr < 4; rr++) {
                        float hv = (kk == 0) ? hr[rr].x : (kk == 1) ? hr[rr].y
                                 : (kk == 2) ? hr[rr].z : hr[rr].w;
                        f[rr].x = fmaf(hv, wv.x, f[rr].x);
                        f[rr].y = fmaf(hv, wv.y, f[rr].y);
                    }
                }
            }
            float pd[4], sl[4];
            #pragma unroll
            for (int rr = 0; rr < 4; rr++) {
                float2 zo = *(const float2*)(sZ + (r0 + rr) * ZD + c2);
                zo.x = fmaf(dt, f[rr].x, zo.x);
                zo.y = fmaf(dt, f[rr].y, zo.y);
                *(float2*)(sZ + (r0 + rr) * ZD + c2) = zo;
                pd[rr] = zo.x * dv0.x + zo.y * dv0.y;
                sl[rr] = zo.x * dv1.x + zo.y * dv1.y;
            }
            __syncwarp();
            #pragma unroll
            for (int rr = 0; rr < 4; rr++) {
                float p = pd[rr], q = sl[rr];
                #pragma unroll
                for (int o = 16; o; o >>= 1) {
                    p += __shfl_xor_sync(FULL, p, o);
                    q += __shfl_xor_sync(FULL, q, o);
                }
                if (l == 0) {
                    size_t row = (size_t)(rowBase + r0 + rr);
                    outPd[row * TOUT + (t + 1)] = p + db0;
                    outSl[row * TOUT + (t + 1)] = q + db1v;
                }
            }
        }
    }
}

// ---------------------------------------------------------------------------
// Launch
// ---------------------------------------------------------------------------
extern "C" void kernel_launch(void* const* d_in, const int* in_sizes, int n_in,
                              void* d_out, int out_size)
{
    const float* bert  = (const float*)d_in[0];
    // d_in[1] = times (unused: only its static shape matters)
    // d_in[2] = seq_lens (unused)
    const float* eps   = (const float*)d_in[3];
    const float* projW = (const float*)d_in[4];
    const float* projB = (const float*)d_in[5];
    const float* lnG   = (const float*)d_in[6];
    const float* lnB   = (const float*)d_in[7];
    const float* lns   = (const float*)d_in[8];
    const float* dW1   = (const float*)d_in[9];
    const float* db1   = (const float*)d_in[10];
    const float* dW2   = (const float*)d_in[11];
    const float* db2   = (const float*)d_in[12];
    const float* oW1   = (const float*)d_in[13];
    const float* ob1   = (const float*)d_in[14];
    const float* oW2   = (const float*)d_in[15];
    const float* ob2   = (const float*)d_in[16];
    const float* oW3   = (const float*)d_in[17];
    const float* ob3   = (const float*)d_in[18];
    const float* decW  = (const float*)d_in[19];
    const float* decB  = (const float*)d_in[20];

    float* out    = (float*)d_out;
    float* outPd  = out;
    float* outSl  = out + (size_t)BN * TOUT;
    float* outDif = out + 2 * (size_t)BN * TOUT;

    phaseA_kernel<<<512, 256>>>(bert, eps, projW, projB, lnG, lnB, lns,
                                dW1, db1, dW2, db2, decW, decB, outPd, outSl);
    reduceDiff_kernel<<<1, 256>>>(outDif);

    size_t smemFloats = (size_t)(ZD * OU + OU * OU + OU * ZD      // weights
                                 + OU + OU + ZD + ZD + ZD          // biases + dec
                                 + ROWS * ZD + ROWS * OU + ROWS * OU); // z, h1, h2
    size_t smemBytes = smemFloats * sizeof(float);
    cudaFuncSetAttribute(ode_kernel, cudaFuncAttributeMaxDynamicSharedMemorySize,
                         (int)smemBytes);
    ode_kernel<<<BN / ROWS, 256, smemBytes>>>(oW1, ob1, oW2, ob2, oW3, ob3,
                                              decW, decB, outPd, outSl);
}